// round 5
// baseline (speedup 1.0000x reference)
#include <cuda_runtime.h>
#include <math.h>

// ---------------------------------------------------------------------------
// RWKV7 attention block, B=4 T=2048 H=1024 NH=16 HD=64, fp32 end-to-end.
// Pipeline:
//   prep (token shift mixes) -> SGEMMs (proj + LoRA) -> postproj (kk norm etc)
//   -> sequential scan -> groupnorm+corr+gate -> output SGEMM
// ---------------------------------------------------------------------------

#define BB   4
#define TT   2048
#define HH   1024
#define HDD  64
#define NHH  16
#define BT   (BB*TT)        // 8192 tokens
#define BTH  (BT*HH)        // 8388608
#define DECAY_LOG_SCALE (-0.6065306597126334f)
#define GN_EPS (64.0f*1e-5f)

// ----------------------------- scratch ------------------------------------
static __device__ float g_xr[BTH], g_xw[BTH], g_xk[BTH], g_xv[BTH], g_xa[BTH], g_xg[BTH];
static __device__ float g_r[BTH], g_ew[BTH], g_k[BTH], g_v0[BTH], g_v[BTH], g_a[BTH];
static __device__ float g_an[BTH], g_bv[BTH], g_g[BTH], g_o[BTH], g_y[BTH];
static __device__ float g_t1[BT*64], g_t2[BT*64], g_t3[BT*64], g_t4[BT*160];

__device__ __forceinline__ float sigf(float x) { return 1.0f / (1.0f + expf(-x)); }

// ----------------------------- prep: token shift ---------------------------
__global__ void prep_kernel(const float* __restrict__ hs,
                            const float* __restrict__ mr, const float* __restrict__ mw,
                            const float* __restrict__ mk, const float* __restrict__ mv,
                            const float* __restrict__ ma, const float* __restrict__ mg)
{
    int i4 = blockIdx.x * blockDim.x + threadIdx.x;
    if (i4 >= BTH / 4) return;
    int i = i4 * 4;
    int t = (i / HH) % TT;
    int h = i % HH;
    float4 x = *(const float4*)(hs + i);
    float4 p = make_float4(0.f, 0.f, 0.f, 0.f);
    if (t > 0) p = *(const float4*)(hs + i - HH);
    float4 d = make_float4(p.x - x.x, p.y - x.y, p.z - x.z, p.w - x.w);
#define DOMIX(dst, mp) { float4 m4 = *(const float4*)((mp) + h); float4 o4; \
    o4.x = fmaf(d.x, m4.x, x.x); o4.y = fmaf(d.y, m4.y, x.y); \
    o4.z = fmaf(d.z, m4.z, x.z); o4.w = fmaf(d.w, m4.w, x.w); \
    *(float4*)((dst) + i) = o4; }
    DOMIX(g_xr, mr) DOMIX(g_xw, mw) DOMIX(g_xk, mk)
    DOMIX(g_xv, mv) DOMIX(g_xa, ma) DOMIX(g_xg, mg)
#undef DOMIX
}

// ----------------------------- SGEMM (fp32, 64x64x16 tile) -----------------
// EPI: 0 none, 1 tanh, 2 sigmoid, 3 sigmoid(+bias), 4 exp(DECAY*sigmoid(+bias)),
//      5 v-lerp: e0 + sig(acc+bias)*(e1 - e0)
template <int EPI>
__global__ void __launch_bounds__(256)
sgemm_kernel(const float* __restrict__ A, const float* __restrict__ Bm,
             float* __restrict__ C, int M, int N, int K,
             const float* __restrict__ bias,
             const float* __restrict__ e0, const float* __restrict__ e1)
{
    constexpr int BK = 16;
    __shared__ float As[BK][68];
    __shared__ float Bs[BK][64];
    int tid = threadIdx.x;
    int tx = tid & 15, ty = tid >> 4;
    int m0 = blockIdx.y * 64, n0 = blockIdx.x * 64;
    int ar = tid >> 2, ac = (tid & 3) << 2;     // A: row in tile, col4
    int br = tid >> 4, bc = (tid & 15) << 2;    // B: row in tile, col4
    float acc[4][4];
#pragma unroll
    for (int i = 0; i < 4; i++)
#pragma unroll
        for (int j = 0; j < 4; j++) acc[i][j] = 0.f;

    const float* Ap = A + (size_t)(m0 + ar) * K + ac;
    const float* Bp = Bm + (size_t)br * N + n0 + bc;
    bool bvalid = (n0 + bc) < N;

    for (int k0 = 0; k0 < K; k0 += BK) {
        float4 av = *(const float4*)(Ap + k0);
        As[ac + 0][ar] = av.x; As[ac + 1][ar] = av.y;
        As[ac + 2][ar] = av.z; As[ac + 3][ar] = av.w;
        float4 bv4 = make_float4(0.f, 0.f, 0.f, 0.f);
        if (bvalid) bv4 = *(const float4*)(Bp + (size_t)k0 * N);
        *(float4*)&Bs[br][bc] = bv4;
        __syncthreads();
#pragma unroll
        for (int kk = 0; kk < BK; kk++) {
            float4 a4 = *(const float4*)&As[kk][ty << 2];
            float4 b4 = *(const float4*)&Bs[kk][tx << 2];
            float aa[4] = {a4.x, a4.y, a4.z, a4.w};
            float bb[4] = {b4.x, b4.y, b4.z, b4.w};
#pragma unroll
            for (int i = 0; i < 4; i++)
#pragma unroll
                for (int j = 0; j < 4; j++)
                    acc[i][j] = fmaf(aa[i], bb[j], acc[i][j]);
        }
        __syncthreads();
    }

#pragma unroll
    for (int i = 0; i < 4; i++) {
        int row = m0 + (ty << 2) + i;
#pragma unroll
        for (int j = 0; j < 4; j++) {
            int col = n0 + (tx << 2) + j;
            if (col < N) {
                float val = acc[i][j];
                if (EPI == 1) val = tanhf(val);
                else if (EPI == 2) val = sigf(val);
                else if (EPI == 3) val = sigf(val + bias[col]);
                else if (EPI == 4) val = expf(DECAY_LOG_SCALE * sigf(val + bias[col]));
                else if (EPI == 5) {
                    float a0 = e0[(size_t)row * N + col];
                    float b0 = e1[(size_t)row * N + col];
                    val = a0 + sigf(val + bias[col]) * (b0 - a0);
                }
                C[(size_t)row * N + col] = val;
            }
        }
    }
}

// --------------------- postproj: kk-normalize, k scale, a/b vecs -----------
__global__ void postproj_kernel(const float* __restrict__ kkw,
                                const float* __restrict__ kaw)
{
    int bt = blockIdx.x;
    int h = threadIdx.x;
    int head = h >> 6;
    int idx = bt * HH + h;
    float kv = g_k[idx], av = g_a[idx];
    float kkx = kv * kkw[h];
    float ss = kkx * kkx;
#pragma unroll
    for (int m = 16; m >= 1; m >>= 1) ss += __shfl_xor_sync(~0u, ss, m);
    __shared__ float ws[32];
    if ((h & 31) == 0) ws[h >> 5] = ss;
    __syncthreads();
    float tot = ws[head * 2] + ws[head * 2 + 1];
    float inv = 1.0f / fmaxf(sqrtf(tot), 1e-12f);
    float kkn = kkx * inv;
    g_an[idx] = -kkn;
    g_bv[idx] = kkn * av;
    g_k[idx] = kv * (1.0f + (av - 1.0f) * kaw[h]);
}

// ----------------------------- sequential scan ------------------------------
// 128 CTAs: (b,h) pair x 2 row-splits of 32 rows. 256 threads: 32 rows x 8 lanes,
// each lane owns 8 state columns. Double-buffered shared staging of step vectors.
__global__ void __launch_bounds__(256) scan_kernel()
{
    __shared__ float sh[2][6][64];      // slots: 0=r 1=ew 2=k 3=v 4=-kk 5=kk*a
    int pair = blockIdx.x >> 1;
    int rsplit = blockIdx.x & 1;
    int tid = threadIdx.x;
    int vloc = tid >> 3;
    int q = tid & 7;
    int vrow = rsplit * 32 + vloc;
    int b = pair >> 4, h = pair & 15;
    int base0 = b * TT * HH + h * HDD;

    const float* lp = nullptr;
    float* sd0 = nullptr; float* sd1 = nullptr;
    if (tid < 96) {
        int aid = tid >> 4, wq = tid & 15;
        switch (aid) {
            case 0: lp = g_r;  break;
            case 1: lp = g_ew; break;
            case 2: lp = g_k;  break;
            case 3: lp = g_v;  break;
            case 4: lp = g_an; break;
            default: lp = g_bv; break;
        }
        lp += base0 + (wq << 2);
        sd0 = &sh[0][aid][wq << 2];
        sd1 = &sh[1][aid][wq << 2];
    }

    float S[8];
#pragma unroll
    for (int j = 0; j < 8; j++) S[j] = 0.f;

    if (tid < 96) *(float4*)sd0 = *(const float4*)lp;
    __syncthreads();

    for (int t = 0; t < TT; t++) {
        int cur = t & 1;
        if (tid < 96 && t + 1 < TT) {
            float4 tmp = *(const float4*)(lp + (size_t)(t + 1) * HH);
            *(float4*)(cur ? sd0 : sd1) = tmp;
        }
        const float (*cs)[64] = sh[cur];
        int c0 = q << 3;

        float4 aA = *(const float4*)&cs[4][c0];
        float4 aB = *(const float4*)&cs[4][c0 + 4];
        float sa = S[0]*aA.x + S[1]*aA.y + S[2]*aA.z + S[3]*aA.w
                 + S[4]*aB.x + S[5]*aB.y + S[6]*aB.z + S[7]*aB.w;
        sa += __shfl_xor_sync(~0u, sa, 1);
        sa += __shfl_xor_sync(~0u, sa, 2);
        sa += __shfl_xor_sync(~0u, sa, 4);

        float vv = cs[3][vrow];
        float4 eA = *(const float4*)&cs[1][c0];
        float4 eB = *(const float4*)&cs[1][c0 + 4];
        float4 kA = *(const float4*)&cs[2][c0];
        float4 kB = *(const float4*)&cs[2][c0 + 4];
        float4 bA = *(const float4*)&cs[5][c0];
        float4 bB = *(const float4*)&cs[5][c0 + 4];

        S[0] = fmaf(S[0], eA.x, fmaf(sa, bA.x, vv * kA.x));
        S[1] = fmaf(S[1], eA.y, fmaf(sa, bA.y, vv * kA.y));
        S[2] = fmaf(S[2], eA.z, fmaf(sa, bA.z, vv * kA.z));
        S[3] = fmaf(S[3], eA.w, fmaf(sa, bA.w, vv * kA.w));
        S[4] = fmaf(S[4], eB.x, fmaf(sa, bB.x, vv * kB.x));
        S[5] = fmaf(S[5], eB.y, fmaf(sa, bB.y, vv * kB.y));
        S[6] = fmaf(S[6], eB.z, fmaf(sa, bB.z, vv * kB.z));
        S[7] = fmaf(S[7], eB.w, fmaf(sa, bB.w, vv * kB.w));

        float4 rA = *(const float4*)&cs[0][c0];
        float4 rB = *(const float4*)&cs[0][c0 + 4];
        float oo = S[0]*rA.x + S[1]*rA.y + S[2]*rA.z + S[3]*rA.w
                 + S[4]*rB.x + S[5]*rB.y + S[6]*rB.z + S[7]*rB.w;
        oo += __shfl_xor_sync(~0u, oo, 1);
        oo += __shfl_xor_sync(~0u, oo, 2);
        oo += __shfl_xor_sync(~0u, oo, 4);
        if (q == 0) g_o[base0 + t * HH + vrow] = oo;
        __syncthreads();
    }
}

// ---------------- groupnorm + bonus-corr + gate -> y ------------------------
__global__ void finalmix_kernel(const float* __restrict__ rkw,
                                const float* __restrict__ gnw,
                                const float* __restrict__ gnb)
{
    int bt = blockIdx.x;
    int head = threadIdx.x >> 5;
    int ld = threadIdx.x & 31;
    int base = bt * HH + head * HDD;
    int i0 = base + ld, i1 = base + 32 + ld;
    float o0 = g_o[i0], o1 = g_o[i1];
    float r0 = g_r[i0], r1 = g_r[i1];
    float k0 = g_k[i0], k1 = g_k[i1];
    float v0 = g_v[i0], v1 = g_v[i1];
    int h0 = head * HDD + ld, h1 = h0 + 32;

    float s  = o0 + o1;
    float qq = o0 * o0 + o1 * o1;
    float rk = r0 * k0 * rkw[h0] + r1 * k1 * rkw[h1];
#pragma unroll
    for (int m = 16; m >= 1; m >>= 1) {
        s  += __shfl_xor_sync(~0u, s,  m);
        qq += __shfl_xor_sync(~0u, qq, m);
        rk += __shfl_xor_sync(~0u, rk, m);
    }
    float mu = s * (1.0f / 64.0f);
    float var = qq * (1.0f / 64.0f) - mu * mu;
    float is = rsqrtf(var + GN_EPS);
    float y0 = (fmaf((o0 - mu) * is, gnw[h0], gnb[h0]) + rk * v0) * g_g[i0];
    float y1 = (fmaf((o1 - mu) * is, gnw[h1], gnb[h1]) + rk * v1) * g_g[i1];
    g_y[i0] = y0;
    g_y[i1] = y1;
}

// ----------------------------- host ----------------------------------------
extern "C" void kernel_launch(void* const* d_in, const int* in_sizes, int n_in,
                              void* d_out, int out_size)
{
    const float* hs  = (const float*)d_in[0];
    const float* vfi = (const float*)d_in[1];
    const float* x_r = (const float*)d_in[2];
    const float* x_w = (const float*)d_in[3];
    const float* x_k = (const float*)d_in[4];
    const float* x_v = (const float*)d_in[5];
    const float* x_a = (const float*)d_in[6];
    const float* x_g = (const float*)d_in[7];
    const float* k_k = (const float*)d_in[8];
    const float* k_a = (const float*)d_in[9];
    const float* r_k = (const float*)d_in[10];
    const float* W_r = (const float*)d_in[11];
    const float* W_k = (const float*)d_in[12];
    const float* W_v = (const float*)d_in[13];
    const float* W_o = (const float*)d_in[14];
    const float* wA  = (const float*)d_in[15];
    const float* wB  = (const float*)d_in[16];
    const float* wb  = (const float*)d_in[17];
    const float* vA  = (const float*)d_in[18];
    const float* vB  = (const float*)d_in[19];
    const float* vb  = (const float*)d_in[20];
    const float* aA  = (const float*)d_in[21];
    const float* aB  = (const float*)d_in[22];
    const float* ab  = (const float*)d_in[23];
    const float* gA  = (const float*)d_in[24];
    const float* gB  = (const float*)d_in[25];
    const float* gnw = (const float*)d_in[26];
    const float* gnb = (const float*)d_in[27];

    float *xr, *xw, *xk, *xv, *xa, *xg, *rb, *ewb, *kb, *v0b, *vb2, *ab2;
    float *t1, *t2, *t3, *t4, *gb2, *yb;
    cudaGetSymbolAddress((void**)&xr,  g_xr);
    cudaGetSymbolAddress((void**)&xw,  g_xw);
    cudaGetSymbolAddress((void**)&xk,  g_xk);
    cudaGetSymbolAddress((void**)&xv,  g_xv);
    cudaGetSymbolAddress((void**)&xa,  g_xa);
    cudaGetSymbolAddress((void**)&xg,  g_xg);
    cudaGetSymbolAddress((void**)&rb,  g_r);
    cudaGetSymbolAddress((void**)&ewb, g_ew);
    cudaGetSymbolAddress((void**)&kb,  g_k);
    cudaGetSymbolAddress((void**)&v0b, g_v0);
    cudaGetSymbolAddress((void**)&vb2, g_v);
    cudaGetSymbolAddress((void**)&ab2, g_a);
    cudaGetSymbolAddress((void**)&t1,  g_t1);
    cudaGetSymbolAddress((void**)&t2,  g_t2);
    cudaGetSymbolAddress((void**)&t3,  g_t3);
    cudaGetSymbolAddress((void**)&t4,  g_t4);
    cudaGetSymbolAddress((void**)&gb2, g_g);
    cudaGetSymbolAddress((void**)&yb,  g_y);

    // 1. token-shift mixes
    prep_kernel<<<BTH / 4 / 256, 256>>>(hs, x_r, x_w, x_k, x_v, x_a, x_g);

    dim3 blk(256);
    dim3 gBig(HH / 64, BT / 64);       // 16 x 128
    dim3 g64(1, BT / 64);              // N=64
    dim3 g160(3, BT / 64);             // N=160

    // 2. projections
    sgemm_kernel<0><<<gBig, blk>>>(xr, W_r, rb,  BT, HH, HH, nullptr, nullptr, nullptr);
    sgemm_kernel<0><<<gBig, blk>>>(xk, W_k, kb,  BT, HH, HH, nullptr, nullptr, nullptr);
    sgemm_kernel<0><<<gBig, blk>>>(xv, W_v, v0b, BT, HH, HH, nullptr, nullptr, nullptr);

    // 3. LoRAs
    sgemm_kernel<1><<<g64, blk>>>(xw, wA, t1, BT, 64, HH, nullptr, nullptr, nullptr);   // tanh
    sgemm_kernel<4><<<gBig, blk>>>(t1, wB, ewb, BT, HH, 64, wb, nullptr, nullptr);      // ew = exp(decay*sig)
    sgemm_kernel<0><<<g64, blk>>>(xv, vA, t2, BT, 64, HH, nullptr, nullptr, nullptr);
    sgemm_kernel<5><<<gBig, blk>>>(t2, vB, vb2, BT, HH, 64, vb, v0b, vfi);              // v lerp
    sgemm_kernel<0><<<g64, blk>>>(xa, aA, t3, BT, 64, HH, nullptr, nullptr, nullptr);
    sgemm_kernel<3><<<gBig, blk>>>(t3, aB, ab2, BT, HH, 64, ab, nullptr, nullptr);      // a = sig
    sgemm_kernel<2><<<g160, blk>>>(xg, gA, t4, BT, 160, HH, nullptr, nullptr, nullptr); // sig
    sgemm_kernel<0><<<gBig, blk>>>(t4, gB, gb2, BT, HH, 160, nullptr, nullptr, nullptr);

    // 4. kk normalize / k scale / scan coefficient vectors
    postproj_kernel<<<BT, 1024>>>(k_k, k_a);

    // 5. sequential RWKV7 scan
    scan_kernel<<<128, 256>>>();

    // 6. groupnorm + correction + gate
    finalmix_kernel<<<BT, 512>>>(r_k, gnw, gnb);

    // 7. output projection
    sgemm_kernel<0><<<gBig, blk>>>(yb, W_o, (float*)d_out, BT, HH, HH,
                                   nullptr, nullptr, nullptr);
}

// round 10
// speedup vs baseline: 1.3216x; 1.3216x over previous
#include <cuda_runtime.h>
#include <cuda_bf16.h>
#include <stdint.h>
#include <math.h>

// ---------------------------------------------------------------------------
// RWKV7 attention block, B=4 T=2048 H=1024 NH=16 HD=64.
// Big GEMMs on mma.sync bf16 (hi+lo split, fp32 accum) — tcgen05 is not
// available because the harness emits compute_103 PTX (no 103a features).
// LoRA-down GEMMs on fp32 SGEMM; sequential scan; fused epilogues.
// ---------------------------------------------------------------------------

#define BB   4
#define TT   2048
#define HH   1024
#define HDD  64
#define NHH  16
#define BT   (BB*TT)        // 8192 tokens
#define BTH  (BT*HH)        // 8388608
#define DECAY_LOG_SCALE (-0.6065306597126334f)
#define GN_EPS (64.0f*1e-5f)

// ----------------------------- scratch ------------------------------------
static __device__ float g_xr[BTH], g_xw[BTH], g_xk[BTH], g_xv[BTH], g_xa[BTH], g_xg[BTH];
static __device__ float g_r[BTH], g_ew[BTH], g_k[BTH], g_v0[BTH], g_v[BTH], g_a[BTH];
static __device__ float g_an[BTH], g_bv[BTH], g_g[BTH], g_o[BTH], g_y[BTH];
static __device__ float g_t1[BT*64], g_t2[BT*64], g_t3[BT*64], g_t4[BT*160];

// transposed + bf16-split weights ([N,K] K-major)
static __device__ __nv_bfloat16 g_WrH[HH*HH], g_WrL[HH*HH];
static __device__ __nv_bfloat16 g_WkH[HH*HH], g_WkL[HH*HH];
static __device__ __nv_bfloat16 g_WvH[HH*HH], g_WvL[HH*HH];
static __device__ __nv_bfloat16 g_WoH[HH*HH], g_WoL[HH*HH];
static __device__ __nv_bfloat16 g_wBH[HH*64], g_wBL[HH*64];
static __device__ __nv_bfloat16 g_vBH[HH*64], g_vBL[HH*64];
static __device__ __nv_bfloat16 g_aBH[HH*64], g_aBL[HH*64];
static __device__ __nv_bfloat16 g_gBH[HH*160], g_gBL[HH*160];

__device__ __forceinline__ float sigf(float x) { return 1.0f / (1.0f + expf(-x)); }

__device__ __forceinline__ uint32_t pack_bf2(__nv_bfloat16 lo, __nv_bfloat16 hi) {
    return (uint32_t)__bfloat16_as_ushort(lo) | ((uint32_t)__bfloat16_as_ushort(hi) << 16);
}

__device__ __forceinline__ uint32_t smem_u32(const void* p) {
    uint32_t a;
    asm("{ .reg .u64 t; cvta.to.shared.u64 t, %1; cvt.u32.u64 %0, t; }" : "=r"(a) : "l"(p));
    return a;
}

__device__ __forceinline__ void ldsm4(uint32_t& r0, uint32_t& r1, uint32_t& r2, uint32_t& r3,
                                      uint32_t addr)
{
    asm volatile("ldmatrix.sync.aligned.m8n8.x4.shared.b16 {%0,%1,%2,%3}, [%4];"
                 : "=r"(r0), "=r"(r1), "=r"(r2), "=r"(r3) : "r"(addr));
}

__device__ __forceinline__ void mma16816(float* c,
                                         uint32_t a0, uint32_t a1, uint32_t a2, uint32_t a3,
                                         uint32_t b0, uint32_t b1)
{
    asm volatile("mma.sync.aligned.m16n8k16.row.col.f32.bf16.bf16.f32 "
                 "{%0,%1,%2,%3}, {%4,%5,%6,%7}, {%8,%9}, {%0,%1,%2,%3};"
                 : "+f"(c[0]), "+f"(c[1]), "+f"(c[2]), "+f"(c[3])
                 : "r"(a0), "r"(a1), "r"(a2), "r"(a3), "r"(b0), "r"(b1));
}

// ----------------------------- prep: token shift ---------------------------
__global__ void prep_kernel(const float* __restrict__ hs,
                            const float* __restrict__ mr, const float* __restrict__ mw,
                            const float* __restrict__ mk, const float* __restrict__ mv,
                            const float* __restrict__ ma, const float* __restrict__ mg)
{
    int i4 = blockIdx.x * blockDim.x + threadIdx.x;
    if (i4 >= BTH / 4) return;
    int i = i4 * 4;
    int t = (i / HH) % TT;
    int h = i % HH;
    float4 x = *(const float4*)(hs + i);
    float4 p = make_float4(0.f, 0.f, 0.f, 0.f);
    if (t > 0) p = *(const float4*)(hs + i - HH);
    float4 d = make_float4(p.x - x.x, p.y - x.y, p.z - x.z, p.w - x.w);
#define DOMIX(dst, mp) { float4 m4 = *(const float4*)((mp) + h); float4 o4; \
    o4.x = fmaf(d.x, m4.x, x.x); o4.y = fmaf(d.y, m4.y, x.y); \
    o4.z = fmaf(d.z, m4.z, x.z); o4.w = fmaf(d.w, m4.w, x.w); \
    *(float4*)((dst) + i) = o4; }
    DOMIX(g_xr, mr) DOMIX(g_xw, mw) DOMIX(g_xk, mk)
    DOMIX(g_xv, mv) DOMIX(g_xa, ma) DOMIX(g_xg, mg)
#undef DOMIX
}

// ----------------- weight transpose + bf16 hi/lo split ---------------------
// in: W (K,N) fp32 row-major; out: Bh/Bl (N,K) bf16.
__global__ void convw_kernel(const float* __restrict__ W,
                             __nv_bfloat16* __restrict__ Bh,
                             __nv_bfloat16* __restrict__ Bl, int K, int N)
{
    __shared__ float ts[32][33];
    int kb = blockIdx.y * 32, nb = blockIdx.x * 32;
    int tx = threadIdx.x, ty = threadIdx.y;  // 32 x 8
    for (int i = ty; i < 32; i += 8)
        ts[i][tx] = W[(size_t)(kb + i) * N + nb + tx];
    __syncthreads();
    for (int i = ty; i < 32; i += 8) {
        float x = ts[tx][i];                 // W[kb+tx][nb+i]
        __nv_bfloat16 h = __float2bfloat16(x);
        __nv_bfloat16 l = __float2bfloat16(x - __bfloat162float(h));
        size_t o = (size_t)(nb + i) * K + kb + tx;
        Bh[o] = h; Bl[o] = l;
    }
}

// --------------------- mma.sync GEMM: C = A @ Bt^T -------------------------
// A: (M,K) fp32, split on the fly to bf16 hi/lo. Bt: (N,K) bf16 hi/lo.
// CTA tile 128x128, BK=32, 8 warps (2x4), warp tile 64x32.
// 3-product split: Ah*Bh + Ah*Bl + Al*Bh in fp32 accumulators.
// EPI: 0 none, 3 sigmoid(+bias), 4 exp(DECAY*sigmoid(+bias)),
//      5 v-lerp e0 + sig(acc+bias)*(e1-e0)
#define LDS 40                       // padded row length (bf16 elems)
#define ABUF (128*LDS)               // elems per matrix (one of hi/lo)
#define TG_SMEM (4*ABUF*2*2)         // A(2bufs:hi+lo) + B(2bufs:hi+lo), bytes = 81920

template <int EPI>
__global__ void __launch_bounds__(256)
tgemm_kernel(const float* __restrict__ A,
             const __nv_bfloat16* __restrict__ Bh, const __nv_bfloat16* __restrict__ Bl,
             float* __restrict__ C, int M, int N, int K,
             const float* __restrict__ bias,
             const float* __restrict__ e0, const float* __restrict__ e1)
{
    extern __shared__ char smem[];
    __nv_bfloat16* As = (__nv_bfloat16*)smem;             // [2 bufs][2 hl][128][LDS]
    __nv_bfloat16* Bs = (__nv_bfloat16*)(smem + 2*2*ABUF*2);
    const int tid = threadIdx.x;
    const int wid = tid >> 5, lane = tid & 31;
    const int wm = wid >> 2, wn = wid & 3;
    const int m0 = blockIdx.y * 128, n0 = blockIdx.x * 128;

    float acc[4][4][4];
#pragma unroll
    for (int i = 0; i < 4; i++)
#pragma unroll
        for (int j = 0; j < 4; j++)
#pragma unroll
            for (int f = 0; f < 4; f++) acc[i][j][f] = 0.f;

    float4 aReg[4];
    uint4 bhReg[2], blReg[2];

    const int nC = K >> 5;

    // ---- load tile k-chunk kc into staging regs ----
#define LOAD_REGS(kc) { \
        int k0 = (kc) << 5; \
        _Pragma("unroll") \
        for (int i = 0; i < 4; i++) { \
            int idx = tid + i * 256; \
            int r = idx >> 3, c4 = (idx & 7) << 2; \
            aReg[i] = *(const float4*)(A + (size_t)(m0 + r) * K + k0 + c4); \
        } \
        _Pragma("unroll") \
        for (int i = 0; i < 2; i++) { \
            int idx = tid + i * 256; \
            int r = idx >> 2, c8 = (idx & 3) << 3; \
            size_t go = (size_t)(n0 + r) * K + k0 + c8; \
            bhReg[i] = *(const uint4*)(Bh + go); \
            blReg[i] = *(const uint4*)(Bl + go); \
        } }

    // ---- split + store staging regs into smem buffer b ----
#define STORE_SMEM(b) { \
        __nv_bfloat16* aH = As + (b) * 2 * ABUF; \
        __nv_bfloat16* aL = aH + ABUF; \
        __nv_bfloat16* bH = Bs + (b) * 2 * ABUF; \
        __nv_bfloat16* bL = bH + ABUF; \
        _Pragma("unroll") \
        for (int i = 0; i < 4; i++) { \
            int idx = tid + i * 256; \
            int r = idx >> 3, c4 = (idx & 7) << 2; \
            float4 v = aReg[i]; \
            __nv_bfloat16 hx = __float2bfloat16(v.x); \
            __nv_bfloat16 hy = __float2bfloat16(v.y); \
            __nv_bfloat16 hz = __float2bfloat16(v.z); \
            __nv_bfloat16 hw = __float2bfloat16(v.w); \
            __nv_bfloat16 lx = __float2bfloat16(v.x - __bfloat162float(hx)); \
            __nv_bfloat16 ly = __float2bfloat16(v.y - __bfloat162float(hy)); \
            __nv_bfloat16 lz = __float2bfloat16(v.z - __bfloat162float(hz)); \
            __nv_bfloat16 lw = __float2bfloat16(v.w - __bfloat162float(hw)); \
            uint2 hv2, lv2; \
            hv2.x = pack_bf2(hx, hy); hv2.y = pack_bf2(hz, hw); \
            lv2.x = pack_bf2(lx, ly); lv2.y = pack_bf2(lz, lw); \
            *(uint2*)(aH + r * LDS + c4) = hv2; \
            *(uint2*)(aL + r * LDS + c4) = lv2; \
        } \
        _Pragma("unroll") \
        for (int i = 0; i < 2; i++) { \
            int idx = tid + i * 256; \
            int r = idx >> 2, c8 = (idx & 3) << 3; \
            *(uint4*)(bH + r * LDS + c8) = bhReg[i]; \
            *(uint4*)(bL + r * LDS + c8) = blReg[i]; \
        } }

    LOAD_REGS(0)
    STORE_SMEM(0)
    __syncthreads();

    for (int ic = 0; ic < nC; ic++) {
        int buf = ic & 1;
        if (ic + 1 < nC) LOAD_REGS(ic + 1)

        // ---- compute on smem[buf] ----
        {
            uint32_t aBaseH = smem_u32(As + buf * 2 * ABUF);
            uint32_t aBaseL = aBaseH + ABUF * 2;
            uint32_t bBaseH = smem_u32(Bs + buf * 2 * ABUF);
            uint32_t bBaseL = bBaseH + ABUF * 2;
#pragma unroll
            for (int kk = 0; kk < 32; kk += 16) {
                uint32_t ah[4][4], al[4][4], bh[2][4], bl[2][4];
#pragma unroll
                for (int i = 0; i < 4; i++) {
                    int row = wm * 64 + i * 16 + (lane & 15);
                    int col = kk + ((lane >> 4) << 3);
                    uint32_t off = (uint32_t)(row * LDS + col) * 2;
                    ldsm4(ah[i][0], ah[i][1], ah[i][2], ah[i][3], aBaseH + off);
                    ldsm4(al[i][0], al[i][1], al[i][2], al[i][3], aBaseL + off);
                }
#pragma unroll
                for (int jp = 0; jp < 2; jp++) {
                    int row = wn * 32 + jp * 16 + ((lane >> 4) << 3) + (lane & 7);
                    int col = kk + ((lane >> 3) & 1) * 8;
                    uint32_t off = (uint32_t)(row * LDS + col) * 2;
                    ldsm4(bh[jp][0], bh[jp][1], bh[jp][2], bh[jp][3], bBaseH + off);
                    ldsm4(bl[jp][0], bl[jp][1], bl[jp][2], bl[jp][3], bBaseL + off);
                }
#pragma unroll
                for (int i = 0; i < 4; i++)
#pragma unroll
                    for (int j = 0; j < 4; j++) {
                        uint32_t b0h = bh[j >> 1][(j & 1) * 2], b1h = bh[j >> 1][(j & 1) * 2 + 1];
                        uint32_t b0l = bl[j >> 1][(j & 1) * 2], b1l = bl[j >> 1][(j & 1) * 2 + 1];
                        mma16816(acc[i][j], ah[i][0], ah[i][1], ah[i][2], ah[i][3], b0h, b1h);
                        mma16816(acc[i][j], ah[i][0], ah[i][1], ah[i][2], ah[i][3], b0l, b1l);
                        mma16816(acc[i][j], al[i][0], al[i][1], al[i][2], al[i][3], b0h, b1h);
                    }
            }
        }

        if (ic + 1 < nC) {
            __syncthreads();          // all warps done reading buf^1 (from iter ic-1)
            STORE_SMEM(buf ^ 1)
            __syncthreads();
        }
    }

    // ---- epilogue: fragment -> C with fused activation ----
    int g = lane >> 2, tig = lane & 3;
#pragma unroll
    for (int i = 0; i < 4; i++) {
        int r0 = m0 + wm * 64 + i * 16 + g;
#pragma unroll
        for (int j = 0; j < 4; j++) {
            int col = n0 + wn * 32 + j * 8 + tig * 2;
            float2 v0 = make_float2(acc[i][j][0], acc[i][j][1]);
            float2 v1 = make_float2(acc[i][j][2], acc[i][j][3]);
            if (EPI == 3 || EPI == 4 || EPI == 5) {
                float b0 = bias[col], b1 = bias[col + 1];
                v0.x = sigf(v0.x + b0); v0.y = sigf(v0.y + b1);
                v1.x = sigf(v1.x + b0); v1.y = sigf(v1.y + b1);
                if (EPI == 4) {
                    v0.x = expf(DECAY_LOG_SCALE * v0.x); v0.y = expf(DECAY_LOG_SCALE * v0.y);
                    v1.x = expf(DECAY_LOG_SCALE * v1.x); v1.y = expf(DECAY_LOG_SCALE * v1.y);
                } else if (EPI == 5) {
                    size_t o0 = (size_t)r0 * N + col, o1 = (size_t)(r0 + 8) * N + col;
                    float2 a0 = *(const float2*)(e0 + o0);
                    float2 c0v = *(const float2*)(e1 + o0);
                    float2 a1 = *(const float2*)(e0 + o1);
                    float2 c1v = *(const float2*)(e1 + o1);
                    v0.x = fmaf(v0.x, c0v.x - a0.x, a0.x);
                    v0.y = fmaf(v0.y, c0v.y - a0.y, a0.y);
                    v1.x = fmaf(v1.x, c1v.x - a1.x, a1.x);
                    v1.y = fmaf(v1.y, c1v.y - a1.y, a1.y);
                }
            }
            *(float2*)(C + (size_t)r0 * N + col) = v0;
            *(float2*)(C + (size_t)(r0 + 8) * N + col) = v1;
        }
    }
}

// ----------------------------- SGEMM (fp32, 64x64x16 tile) -----------------
// Still used for the small-N LoRA down-projections.
// EPI: 0 none, 1 tanh, 2 sigmoid
template <int EPI>
__global__ void __launch_bounds__(256)
sgemm_kernel(const float* __restrict__ A, const float* __restrict__ Bm,
             float* __restrict__ C, int M, int N, int K)
{
    constexpr int BK = 16;
    __shared__ float As[BK][68];
    __shared__ float Bs[BK][64];
    int tid = threadIdx.x;
    int tx = tid & 15, ty = tid >> 4;
    int m0 = blockIdx.y * 64, n0 = blockIdx.x * 64;
    int ar = tid >> 2, ac = (tid & 3) << 2;
    int br = tid >> 4, bc = (tid & 15) << 2;
    float acc[4][4];
#pragma unroll
    for (int i = 0; i < 4; i++)
#pragma unroll
        for (int j = 0; j < 4; j++) acc[i][j] = 0.f;

    const float* Ap = A + (size_t)(m0 + ar) * K + ac;
    const float* Bp = Bm + (size_t)br * N + n0 + bc;
    bool bvalid = (n0 + bc) < N;

    for (int k0 = 0; k0 < K; k0 += BK) {
        float4 av = *(const float4*)(Ap + k0);
        As[ac + 0][ar] = av.x; As[ac + 1][ar] = av.y;
        As[ac + 2][ar] = av.z; As[ac + 3][ar] = av.w;
        float4 bv4 = make_float4(0.f, 0.f, 0.f, 0.f);
        if (bvalid) bv4 = *(const float4*)(Bp + (size_t)k0 * N);
        *(float4*)&Bs[br][bc] = bv4;
        __syncthreads();
#pragma unroll
        for (int kk = 0; kk < BK; kk++) {
            float4 a4 = *(const float4*)&As[kk][ty << 2];
            float4 b4 = *(const float4*)&Bs[kk][tx << 2];
            float aa[4] = {a4.x, a4.y, a4.z, a4.w};
            float bb[4] = {b4.x, b4.y, b4.z, b4.w};
#pragma unroll
            for (int i = 0; i < 4; i++)
#pragma unroll
                for (int j = 0; j < 4; j++)
                    acc[i][j] = fmaf(aa[i], bb[j], acc[i][j]);
        }
        __syncthreads();
    }

#pragma unroll
    for (int i = 0; i < 4; i++) {
        int row = m0 + (ty << 2) + i;
#pragma unroll
        for (int j = 0; j < 4; j++) {
            int col = n0 + (tx << 2) + j;
            if (col < N) {
                float val = acc[i][j];
                if (EPI == 1) val = tanhf(val);
                else if (EPI == 2) val = sigf(val);
                C[(size_t)row * N + col] = val;
            }
        }
    }
}

// --------------------- postproj: kk-normalize, k scale, a/b vecs -----------
__global__ void postproj_kernel(const float* __restrict__ kkw,
                                const float* __restrict__ kaw)
{
    int bt = blockIdx.x;
    int h = threadIdx.x;
    int head = h >> 6;
    int idx = bt * HH + h;
    float kv = g_k[idx], av = g_a[idx];
    float kkx = kv * kkw[h];
    float ss = kkx * kkx;
#pragma unroll
    for (int m = 16; m >= 1; m >>= 1) ss += __shfl_xor_sync(~0u, ss, m);
    __shared__ float ws[32];
    if ((h & 31) == 0) ws[h >> 5] = ss;
    __syncthreads();
    float tot = ws[head * 2] + ws[head * 2 + 1];
    float inv = 1.0f / fmaxf(sqrtf(tot), 1e-12f);
    float kkn = kkx * inv;
    g_an[idx] = -kkn;
    g_bv[idx] = kkn * av;
    g_k[idx] = kv * (1.0f + (av - 1.0f) * kaw[h]);
}

// ----------------------------- sequential scan ------------------------------
__global__ void __launch_bounds__(256) scan_kernel()
{
    __shared__ float sh[2][6][64];
    int pair = blockIdx.x >> 1;
    int rsplit = blockIdx.x & 1;
    int tid = threadIdx.x;
    int vloc = tid >> 3;
    int q = tid & 7;
    int vrow = rsplit * 32 + vloc;
    int b = pair >> 4, h = pair & 15;
    int base0 = b * TT * HH + h * HDD;

    const float* lp = nullptr;
    float* sd0 = nullptr; float* sd1 = nullptr;
    if (tid < 96) {
        int aid = tid >> 4, wq = tid & 15;
        switch (aid) {
            case 0: lp = g_r;  break;
            case 1: lp = g_ew; break;
            case 2: lp = g_k;  break;
            case 3: lp = g_v;  break;
            case 4: lp = g_an; break;
            default: lp = g_bv; break;
        }
        lp += base0 + (wq << 2);
        sd0 = &sh[0][aid][wq << 2];
        sd1 = &sh[1][aid][wq << 2];
    }

    float S[8];
#pragma unroll
    for (int j = 0; j < 8; j++) S[j] = 0.f;

    if (tid < 96) *(float4*)sd0 = *(const float4*)lp;
    __syncthreads();

    for (int t = 0; t < TT; t++) {
        int cur = t & 1;
        if (tid < 96 && t + 1 < TT) {
            float4 tmp = *(const float4*)(lp + (size_t)(t + 1) * HH);
            *(float4*)(cur ? sd0 : sd1) = tmp;
        }
        const float (*cs)[64] = sh[cur];
        int c0 = q << 3;

        float4 aA = *(const float4*)&cs[4][c0];
        float4 aB = *(const float4*)&cs[4][c0 + 4];
        float sa = S[0]*aA.x + S[1]*aA.y + S[2]*aA.z + S[3]*aA.w
                 + S[4]*aB.x + S[5]*aB.y + S[6]*aB.z + S[7]*aB.w;
        sa += __shfl_xor_sync(~0u, sa, 1);
        sa += __shfl_xor_sync(~0u, sa, 2);
        sa += __shfl_xor_sync(~0u, sa, 4);

        float vv = cs[3][vrow];
        float4 eA = *(const float4*)&cs[1][c0];
        float4 eB = *(const float4*)&cs[1][c0 + 4];
        float4 kA = *(const float4*)&cs[2][c0];
        float4 kB = *(const float4*)&cs[2][c0 + 4];
        float4 bA = *(const float4*)&cs[5][c0];
        float4 bB = *(const float4*)&cs[5][c0 + 4];

        S[0] = fmaf(S[0], eA.x, fmaf(sa, bA.x, vv * kA.x));
        S[1] = fmaf(S[1], eA.y, fmaf(sa, bA.y, vv * kA.y));
        S[2] = fmaf(S[2], eA.z, fmaf(sa, bA.z, vv * kA.z));
        S[3] = fmaf(S[3], eA.w, fmaf(sa, bA.w, vv * kA.w));
        S[4] = fmaf(S[4], eB.x, fmaf(sa, bB.x, vv * kB.x));
        S[5] = fmaf(S[5], eB.y, fmaf(sa, bB.y, vv * kB.y));
        S[6] = fmaf(S[6], eB.z, fmaf(sa, bB.z, vv * kB.z));
        S[7] = fmaf(S[7], eB.w, fmaf(sa, bB.w, vv * kB.w));

        float4 rA = *(const float4*)&cs[0][c0];
        float4 rB = *(const float4*)&cs[0][c0 + 4];
        float oo = S[0]*rA.x + S[1]*rA.y + S[2]*rA.z + S[3]*rA.w
                 + S[4]*rB.x + S[5]*rB.y + S[6]*rB.z + S[7]*rB.w;
        oo += __shfl_xor_sync(~0u, oo, 1);
        oo += __shfl_xor_sync(~0u, oo, 2);
        oo += __shfl_xor_sync(~0u, oo, 4);
        if (q == 0) g_o[base0 + t * HH + vrow] = oo;
        __syncthreads();
    }
}

// ---------------- groupnorm + bonus-corr + gate -> y ------------------------
__global__ void finalmix_kernel(const float* __restrict__ rkw,
                                const float* __restrict__ gnw,
                                const float* __restrict__ gnb)
{
    int bt = blockIdx.x;
    int head = threadIdx.x >> 5;
    int ld = threadIdx.x & 31;
    int base = bt * HH + head * HDD;
    int i0 = base + ld, i1 = base + 32 + ld;
    float o0 = g_o[i0], o1 = g_o[i1];
    float r0 = g_r[i0], r1 = g_r[i1];
    float k0 = g_k[i0], k1 = g_k[i1];
    float v0 = g_v[i0], v1 = g_v[i1];
    int h0 = head * HDD + ld, h1 = h0 + 32;

    float s  = o0 + o1;
    float qq = o0 * o0 + o1 * o1;
    float rk = r0 * k0 * rkw[h0] + r1 * k1 * rkw[h1];
#pragma unroll
    for (int m = 16; m >= 1; m >>= 1) {
        s  += __shfl_xor_sync(~0u, s,  m);
        qq += __shfl_xor_sync(~0u, qq, m);
        rk += __shfl_xor_sync(~0u, rk, m);
    }
    float mu = s * (1.0f / 64.0f);
    float var = qq * (1.0f / 64.0f) - mu * mu;
    float is = rsqrtf(var + GN_EPS);
    float y0 = (fmaf((o0 - mu) * is, gnw[h0], gnb[h0]) + rk * v0) * g_g[i0];
    float y1 = (fmaf((o1 - mu) * is, gnw[h1], gnb[h1]) + rk * v1) * g_g[i1];
    g_y[i0] = y0;
    g_y[i1] = y1;
}

// ----------------------------- host ----------------------------------------
extern "C" void kernel_launch(void* const* d_in, const int* in_sizes, int n_in,
                              void* d_out, int out_size)
{
    const float* hs  = (const float*)d_in[0];
    const float* vfi = (const float*)d_in[1];
    const float* x_r = (const float*)d_in[2];
    const float* x_w = (const float*)d_in[3];
    const float* x_k = (const float*)d_in[4];
    const float* x_v = (const float*)d_in[5];
    const float* x_a = (const float*)d_in[6];
    const float* x_g = (const float*)d_in[7];
    const float* k_k = (const float*)d_in[8];
    const float* k_a = (const float*)d_in[9];
    const float* r_k = (const float*)d_in[10];
    const float* W_r = (const float*)d_in[11];
    const float* W_k = (const float*)d_in[12];
    const float* W_v = (const float*)d_in[13];
    const float* W_o = (const float*)d_in[14];
    const float* wA  = (const float*)d_in[15];
    const float* wB  = (const float*)d_in[16];
    const float* wb  = (const float*)d_in[17];
    const float* vA  = (const float*)d_in[18];
    const float* vB  = (const float*)d_in[19];
    const float* vb  = (const float*)d_in[20];
    const float* aA  = (const float*)d_in[21];
    const float* aB  = (const float*)d_in[22];
    const float* ab  = (const float*)d_in[23];
    const float* gA  = (const float*)d_in[24];
    const float* gB  = (const float*)d_in[25];
    const float* gnw = (const float*)d_in[26];
    const float* gnb = (const float*)d_in[27];

    float *xr, *xw, *xk, *xv, *xa, *xg, *rb, *ewb, *kb, *v0b, *vb2, *ab2;
    float *t1, *t2, *t3, *t4, *gb2, *yb;
    cudaGetSymbolAddress((void**)&xr,  g_xr);
    cudaGetSymbolAddress((void**)&xw,  g_xw);
    cudaGetSymbolAddress((void**)&xk,  g_xk);
    cudaGetSymbolAddress((void**)&xv,  g_xv);
    cudaGetSymbolAddress((void**)&xa,  g_xa);
    cudaGetSymbolAddress((void**)&xg,  g_xg);
    cudaGetSymbolAddress((void**)&rb,  g_r);
    cudaGetSymbolAddress((void**)&ewb, g_ew);
    cudaGetSymbolAddress((void**)&kb,  g_k);
    cudaGetSymbolAddress((void**)&v0b, g_v0);
    cudaGetSymbolAddress((void**)&vb2, g_v);
    cudaGetSymbolAddress((void**)&ab2, g_a);
    cudaGetSymbolAddress((void**)&t1,  g_t1);
    cudaGetSymbolAddress((void**)&t2,  g_t2);
    cudaGetSymbolAddress((void**)&t3,  g_t3);
    cudaGetSymbolAddress((void**)&t4,  g_t4);
    cudaGetSymbolAddress((void**)&gb2, g_g);
    cudaGetSymbolAddress((void**)&yb,  g_y);

    __nv_bfloat16 *WrH, *WrL, *WkH, *WkL, *WvH, *WvL, *WoH, *WoL;
    __nv_bfloat16 *wBH, *wBL, *vBH, *vBL, *aBH, *aBL, *gBH, *gBL;
    cudaGetSymbolAddress((void**)&WrH, g_WrH); cudaGetSymbolAddress((void**)&WrL, g_WrL);
    cudaGetSymbolAddress((void**)&WkH, g_WkH); cudaGetSymbolAddress((void**)&WkL, g_WkL);
    cudaGetSymbolAddress((void**)&WvH, g_WvH); cudaGetSymbolAddress((void**)&WvL, g_WvL);
    cudaGetSymbolAddress((void**)&WoH, g_WoH); cudaGetSymbolAddress((void**)&WoL, g_WoL);
    cudaGetSymbolAddress((void**)&wBH, g_wBH); cudaGetSymbolAddress((void**)&wBL, g_wBL);
    cudaGetSymbolAddress((void**)&vBH, g_vBH); cudaGetSymbolAddress((void**)&vBL, g_vBL);
    cudaGetSymbolAddress((void**)&aBH, g_aBH); cudaGetSymbolAddress((void**)&aBL, g_aBL);
    cudaGetSymbolAddress((void**)&gBH, g_gBH); cudaGetSymbolAddress((void**)&gBL, g_gBL);

    cudaFuncSetAttribute(tgemm_kernel<0>, cudaFuncAttributeMaxDynamicSharedMemorySize, TG_SMEM);
    cudaFuncSetAttribute(tgemm_kernel<3>, cudaFuncAttributeMaxDynamicSharedMemorySize, TG_SMEM);
    cudaFuncSetAttribute(tgemm_kernel<4>, cudaFuncAttributeMaxDynamicSharedMemorySize, TG_SMEM);
    cudaFuncSetAttribute(tgemm_kernel<5>, cudaFuncAttributeMaxDynamicSharedMemorySize, TG_SMEM);

    // 0. weight transpose + bf16 split
    dim3 cblk(32, 8);
    convw_kernel<<<dim3(32, 32), cblk>>>(W_r, WrH, WrL, HH, HH);
    convw_kernel<<<dim3(32, 32), cblk>>>(W_k, WkH, WkL, HH, HH);
    convw_kernel<<<dim3(32, 32), cblk>>>(W_v, WvH, WvL, HH, HH);
    convw_kernel<<<dim3(32, 32), cblk>>>(W_o, WoH, WoL, HH, HH);
    convw_kernel<<<dim3(32, 2),  cblk>>>(wB, wBH, wBL, 64, HH);
    convw_kernel<<<dim3(32, 2),  cblk>>>(vB, vBH, vBL, 64, HH);
    convw_kernel<<<dim3(32, 2),  cblk>>>(aB, aBH, aBL, 64, HH);
    convw_kernel<<<dim3(32, 5),  cblk>>>(gB, gBH, gBL, 160, HH);

    // 1. token-shift mixes
    prep_kernel<<<BTH / 4 / 256, 256>>>(hs, x_r, x_w, x_k, x_v, x_a, x_g);

    dim3 blk(256);
    dim3 gT(HH / 128, BT / 128);       // 8 x 64 tensor-GEMM tiles
    dim3 g64(1, BT / 64);
    dim3 g160(3, BT / 64);

    // 2. projections (mma.sync bf16 split)
    tgemm_kernel<0><<<gT, blk, TG_SMEM>>>(xr, WrH, WrL, rb,  BT, HH, HH, nullptr, nullptr, nullptr);
    tgemm_kernel<0><<<gT, blk, TG_SMEM>>>(xk, WkH, WkL, kb,  BT, HH, HH, nullptr, nullptr, nullptr);
    tgemm_kernel<0><<<gT, blk, TG_SMEM>>>(xv, WvH, WvL, v0b, BT, HH, HH, nullptr, nullptr, nullptr);

    // 3. LoRAs: down-proj on SGEMM, up-proj on mma with fused epilogues
    sgemm_kernel<1><<<g64, blk>>>(xw, wA, t1, BT, 64, HH);                  // tanh
    tgemm_kernel<4><<<gT, blk, TG_SMEM>>>(t1, wBH, wBL, ewb, BT, HH, 64, wb, nullptr, nullptr);
    sgemm_kernel<0><<<g64, blk>>>(xv, vA, t2, BT, 64, HH);
    tgemm_kernel<5><<<gT, blk, TG_SMEM>>>(t2, vBH, vBL, vb2, BT, HH, 64, vb, v0b, vfi);
    sgemm_kernel<0><<<g64, blk>>>(xa, aA, t3, BT, 64, HH);
    tgemm_kernel<3><<<gT, blk, TG_SMEM>>>(t3, aBH, aBL, ab2, BT, HH, 64, ab, nullptr, nullptr);
    sgemm_kernel<2><<<g160, blk>>>(xg, gA, t4, BT, 160, HH);                // sigmoid
    tgemm_kernel<0><<<gT, blk, TG_SMEM>>>(t4, gBH, gBL, gb2, BT, HH, 160, nullptr, nullptr, nullptr);

    // 4. kk normalize / k scale / scan coefficient vectors
    postproj_kernel<<<BT, 1024>>>(k_k, k_a);

    // 5. sequential RWKV7 scan
    scan_kernel<<<128, 256>>>();

    // 6. groupnorm + correction + gate
    finalmix_kernel<<<BT, 512>>>(r_k, gnw, gnb);

    // 7. output projection
    tgemm_kernel<0><<<gT, blk, TG_SMEM>>>(yb, WoH, WoL, (float*)d_out, BT, HH, HH,
                                          nullptr, nullptr, nullptr);
}